// round 9
// baseline (speedup 1.0000x reference)
#include <cuda_runtime.h>
#include <cstdint>

#define BATCHN 64
#define SEQN   512
#define EMBN   256
#define HN     256
#define G4N    1024   // 4*H
#define NCOL   2048   // both directions' gate columns
#define NLAB   10
#define STEPS  64     // steps per lstm sub-kernel
#define NSUB   (SEQN / STEPS)

// ---------------- scratch (device globals; no runtime allocation) ----------
__device__ float g_zx[(size_t)SEQN * BATCHN * NCOL];   // [t][b][col2]  (268 MB)
__device__ float g_h[2][2][HN][BATCHN];                // [dir][buf][unit][batch]
__device__ float g_c[2][HN][BATCHN];                   // cell state across sub-kernels
__device__ unsigned int          g_bar_count;          // zero-init, self-resetting
__device__ volatile unsigned int g_bar_gen;            // monotonic across replays
__device__ unsigned int g_flag[2][64];                 // per-CTA step flags

// ---------------- f32x2 helpers -------------------------------------------
__device__ __forceinline__ uint64_t pack2(float lo, float hi) {
    uint64_t r;
    asm("mov.b64 %0, {%1, %2};" : "=l"(r)
        : "r"(__float_as_uint(lo)), "r"(__float_as_uint(hi)));
    return r;
}
__device__ __forceinline__ void unpack2(uint64_t v, float& lo, float& hi) {
    unsigned a, b;
    asm("mov.b64 {%0, %1}, %2;" : "=r"(a), "=r"(b) : "l"(v));
    lo = __uint_as_float(a); hi = __uint_as_float(b);
}
__device__ __forceinline__ uint64_t ffma2(uint64_t a, uint64_t b, uint64_t c) {
    uint64_t d;
    asm("fma.rn.f32x2 %0, %1, %2, %3;" : "=l"(d) : "l"(a), "l"(b), "l"(c));
    return d;
}
__device__ __forceinline__ uint64_t addf2(uint64_t a, uint64_t b) {
    uint64_t d;
    asm("add.rn.f32x2 %0, %1, %2;" : "=l"(d) : "l"(a), "l"(b));
    return d;
}
__device__ __forceinline__ unsigned ldg_relaxed(const unsigned* p) {
    unsigned v;
    asm volatile("ld.relaxed.gpu.global.u32 %0, [%1];" : "=r"(v) : "l"(p));
    return v;
}
__device__ __forceinline__ void stg_relaxed(unsigned* p, unsigned v) {
    asm volatile("st.relaxed.gpu.global.u32 [%0], %1;" :: "l"(p), "r"(v));
}

__device__ __forceinline__ float sigf(float x) {
    return __fdividef(1.0f, 1.0f + __expf(-x));
}
__device__ __forceinline__ float tanhfast(float x) {
    float e = __expf(2.0f * x);
    return 1.0f - 2.0f * __fdividef(1.0f, e + 1.0f);
}

// ---------------- grid barrier (lstm sub-kernel 0 only; gen monotonic) ----
__device__ __forceinline__ void grid_barrier() {
    __syncthreads();
    if (threadIdx.x == 0) {
        __threadfence();
        unsigned gen = g_bar_gen;
        if (atomicAdd(&g_bar_count, 1u) == gridDim.x - 1u) {
            g_bar_count = 0;
            __threadfence();
            g_bar_gen = gen + 1u;
        } else {
            while (g_bar_gen == gen) { __nanosleep(32); }
        }
        __threadfence();
    }
    __syncthreads();
}

// ============================================================================
// Kernel 1: zx = gather(emb, tokens) @ [Wx_f||Wx_b] + bias
// GEMM M=32768, N=2048, K=256; CTA tile 128x128, thread tile 8Mx8N (f32x2
// over M-pairs).  K-chunk 32 -> 33 KB smem -> 2 CTAs/SM.
// ============================================================================
__global__ void __launch_bounds__(256, 2) zx_gemm_kernel(
    const int*   __restrict__ tokens,
    const float* __restrict__ emb,
    const float* __restrict__ Wx_f, const float* __restrict__ b_f,
    const float* __restrict__ Wx_b, const float* __restrict__ b_b)
{
    __shared__ uint64_t a2_s[32 * 64];   // [k][m-pair] packed {m,m+1}  16 KB
    __shared__ float    b_s[32][128];    // [k][n]                     16 KB
    __shared__ int      tok_s[128];

    const int tid    = threadIdx.x;
    const int mtile  = blockIdx.x >> 4;      // 0..255
    const int ntile  = blockIdx.x & 15;      // 0..15
    const int n2base = ntile * 128;
    const float* wsrc = (n2base < G4N) ? (Wx_f + n2base) : (Wx_b + (n2base - G4N));

    if (tid < 128) {
        int gm = mtile * 128 + tid;          // m = t*64 + b
        tok_s[tid] = tokens[(gm & 63) * SEQN + (gm >> 6)];
    }
    __syncthreads();

    const int mp0 = (tid & 15) * 4;   // m-pair base (4 pairs = 8 rows)
    const int n0  = (tid >> 4) * 8;   // n base (8 cols)

    uint64_t acc[4][8];
#pragma unroll
    for (int p = 0; p < 4; ++p)
#pragma unroll
        for (int j = 0; j < 8; ++j) acc[p][j] = 0ull;

    for (int kc = 0; kc < 8; ++kc) {
        const int kbase = kc * 32;
        if (kc) __syncthreads();

        // stage A: gather 2 emb rows per m-pair, pack f32x2, transpose
#pragma unroll
        for (int i = 0; i < 2; ++i) {
            int task = tid + i * 256;        // 0..511
            int mp   = task & 63;
            int col4 = task >> 6;            // 0..7
            const float* r0 = emb + (size_t)tok_s[2*mp]   * EMBN + kbase + col4*4;
            const float* r1 = emb + (size_t)tok_s[2*mp+1] * EMBN + kbase + col4*4;
            float4 va = *(const float4*)r0;
            float4 vb = *(const float4*)r1;
            a2_s[(col4*4 + 0) * 64 + mp] = pack2(va.x, vb.x);
            a2_s[(col4*4 + 1) * 64 + mp] = pack2(va.y, vb.y);
            a2_s[(col4*4 + 2) * 64 + mp] = pack2(va.z, vb.z);
            a2_s[(col4*4 + 3) * 64 + mp] = pack2(va.w, vb.w);
        }
        // stage B
#pragma unroll
        for (int i = 0; i < 4; ++i) {
            int f4  = tid + i * 256;         // 0..1023
            int row = f4 >> 5;               // 0..31
            int c4  = f4 & 31;
            *(float4*)&b_s[row][c4 * 4] =
                *(const float4*)(wsrc + (size_t)(kbase + row) * G4N + c4 * 4);
        }
        __syncthreads();

#pragma unroll 4
        for (int k = 0; k < 32; ++k) {
            const uint64_t* ak = a2_s + k * 64 + mp0;
            ulonglong2 a01 = *(const ulonglong2*)ak;
            ulonglong2 a23 = *(const ulonglong2*)(ak + 2);
            float4 bv0 = *(const float4*)&b_s[k][n0];
            float4 bv1 = *(const float4*)&b_s[k][n0 + 4];
            uint64_t bb0 = pack2(bv0.x, bv0.x);
            uint64_t bb1 = pack2(bv0.y, bv0.y);
            uint64_t bb2 = pack2(bv0.z, bv0.z);
            uint64_t bb3 = pack2(bv0.w, bv0.w);
            uint64_t bb4 = pack2(bv1.x, bv1.x);
            uint64_t bb5 = pack2(bv1.y, bv1.y);
            uint64_t bb6 = pack2(bv1.z, bv1.z);
            uint64_t bb7 = pack2(bv1.w, bv1.w);
#pragma unroll
            for (int p = 0; p < 4; ++p) {
                uint64_t av = (p == 0) ? a01.x : (p == 1) ? a01.y
                             : (p == 2) ? a23.x : a23.y;
                acc[p][0] = ffma2(av, bb0, acc[p][0]);
                acc[p][1] = ffma2(av, bb1, acc[p][1]);
                acc[p][2] = ffma2(av, bb2, acc[p][2]);
                acc[p][3] = ffma2(av, bb3, acc[p][3]);
                acc[p][4] = ffma2(av, bb4, acc[p][4]);
                acc[p][5] = ffma2(av, bb5, acc[p][5]);
                acc[p][6] = ffma2(av, bb6, acc[p][6]);
                acc[p][7] = ffma2(av, bb7, acc[p][7]);
            }
        }
    }

    // epilogue: + bias, store
    float bias[8];
#pragma unroll
    for (int j = 0; j < 8; ++j) {
        int col2 = n2base + n0 + j;
        bias[j] = (col2 < G4N) ? b_f[col2] : b_b[col2 - G4N];
    }
#pragma unroll
    for (int p = 0; p < 4; ++p) {
        float lo[8], hi[8];
#pragma unroll
        for (int j = 0; j < 8; ++j) {
            unpack2(acc[p][j], lo[j], hi[j]);
            lo[j] += bias[j]; hi[j] += bias[j];
        }
        size_t m = (size_t)(mtile * 128 + 2 * (mp0 + p));
        float* dst = g_zx + m * NCOL + n2base + n0;
        *(float4*)(dst)            = make_float4(lo[0], lo[1], lo[2], lo[3]);
        *(float4*)(dst + 4)        = make_float4(lo[4], lo[5], lo[6], lo[7]);
        *(float4*)(dst + NCOL)     = make_float4(hi[0], hi[1], hi[2], hi[3]);
        *(float4*)(dst + NCOL + 4) = make_float4(hi[4], hi[5], hi[6], hi[7]);
    }
}

// ============================================================================
// Kernel 2 (x8): bidirectional LSTM recurrence, STEPS steps per launch.
// 128 CTAs x 256 threads.  CTA = (dir, unit-group of 8, batch-half of 32).
// Sync = round-4-proven: wait ALL 32 same-batch-half flags (the wait set
// contains every reader of the h buffer -> WAR-safe with 2-deep g_h).
// js(2 j-halves) x ul(8) x bp(16); partials reduced js=1 -> js=0 in smem.
// smem: wh2 64K | h_s 32K | red 4K = 100 KB dynamic.
// ============================================================================
__global__ void __launch_bounds__(256) lstm_kernel(
    const float* __restrict__ Wh_f, const float* __restrict__ Wh_b, int t0)
{
    extern __shared__ unsigned char smraw[];
    uint64_t* wh2 = (uint64_t*)smraw;                        // 64 KB [j][ul][g] {w,w}
    float (*h_s)[32] = (float(*)[32])(smraw + 65536);        // 32 KB [j][lb]
    uint64_t* red = (uint64_t*)(smraw + 98304);              // 4 KB  [ul][bp][4]

    const int tid = threadIdx.x;
    const int cid = blockIdx.x;
    const int dir = cid >> 6;
    const int c6  = cid & 63;
    const int ug  = c6 >> 1;            // 0..31
    const int bh  = c6 & 1;
    const int u0  = ug * 8;
    const int B0  = bh * 32;
    const float* Wh = dir ? Wh_b : Wh_f;

    // stage duplicated Wh pairs: wh2[j*32 + ul*4 + g] = {w,w}
    for (int idx = tid; idx < HN * 32; idx += 256) {
        int j  = idx >> 5;
        int ul = (idx >> 2) & 7;
        int g  = idx & 3;
        float w = Wh[j * G4N + g * HN + u0 + ul];
        wh2[idx] = pack2(w, w);
    }
    if (t0 == 0) {
        if (tid == 0) stg_relaxed(&g_flag[dir][c6], 0u);
        grid_barrier();                 // all flags reset before any poll
    } else {
        __syncthreads();
    }

    const int lane = tid & 31;
    const int wrp  = tid >> 5;
    const int js   = wrp >> 2;                           // j-half
    const int ul   = (wrp & 1) * 4 + (lane & 3);         // 0..7
    const int bp   = ((wrp >> 1) & 1) * 8 + (lane >> 2); // 0..15
    const int lb0  = bp * 2;
    const int b0g  = B0 + lb0;
    const int u    = u0 + ul;
    const uint64_t* wp = wh2 + ul * 4;
    const int jbase = js * 128;
    uint64_t* rslot = red + ((ul << 4) + bp) * 4;

    float c0 = 0.0f, c1 = 0.0f;
    if (t0 > 0 && js == 0) {
        float2 cc = *(float2*)&g_c[dir][u][b0g];
        c0 = cc.x; c1 = cc.y;
    }

    for (int t = t0; t < t0 + STEPS; ++t) {
        const int zt = dir ? (SEQN - 1 - t) : t;
        // z preloads (js=0 only); independent of h -> overlap wait+stage
        float zi0, zf0, zg0, zo0, zi1, zf1, zg1, zo1;
        if (js == 0) {
            const float* zrow = g_zx + ((size_t)zt * BATCHN + b0g) * NCOL
                                    + dir * G4N + u;
            zi0 = __ldg(zrow + 0 * HN);        zf0 = __ldg(zrow + 1 * HN);
            zg0 = __ldg(zrow + 2 * HN);        zo0 = __ldg(zrow + 3 * HN);
            zi1 = __ldg(zrow + NCOL + 0 * HN); zf1 = __ldg(zrow + NCOL + 1 * HN);
            zg1 = __ldg(zrow + NCOL + 2 * HN); zo1 = __ldg(zrow + NCOL + 3 * HN);
        }

        if (t > 0) {
            // wait on ALL 32 same-batch-half CTAs (producers AND readers)
            if (tid < 32) {
                const unsigned* fp = &g_flag[dir][tid * 2 + bh];
                unsigned ok;
                do {
                    unsigned v = ldg_relaxed(fp);
                    ok = __all_sync(0xffffffffu, v >= (unsigned)t);
                } while (!ok);
                __threadfence();
            }
            __syncthreads();
            // stage h_prev for this batch half (32 KB) from L2
#pragma unroll
            for (int i = 0; i < 8; ++i) {
                int f4  = tid + i * 256;
                int j   = f4 >> 3;
                int lb4 = f4 & 7;
                *(float4*)&h_s[j][lb4 * 4] =
                    __ldcg((const float4*)&g_h[dir][t & 1][j][B0 + lb4 * 4]);
            }
            __syncthreads();
        }

        uint64_t ai, af, ag, ao;
        if (js == 0) {
            ai = pack2(zi0, zi1); af = pack2(zf0, zf1);
            ag = pack2(zg0, zg1); ao = pack2(zo0, zo1);
        } else {
            ai = af = ag = ao = 0ull;
        }

        if (t > 0) {
#pragma unroll 8
            for (int j = 0; j < 128; ++j) {
                const int jj = jbase + j;
                uint64_t h2 = *(const uint64_t*)&h_s[jj][lb0];
                ulonglong2 w01 = *(const ulonglong2*)(wp + jj * 32);
                ulonglong2 w23 = *(const ulonglong2*)(wp + jj * 32 + 2);
                ai = ffma2(h2, w01.x, ai);
                af = ffma2(h2, w01.y, af);
                ag = ffma2(h2, w23.x, ag);
                ao = ffma2(h2, w23.y, ao);
            }
        }

        // reduce js=1 partials into js=0
        if (js == 1) {
            rslot[0] = ai; rslot[1] = af; rslot[2] = ag; rslot[3] = ao;
        }
        __syncthreads();
        if (js == 0) {
            ai = addf2(ai, rslot[0]);
            af = addf2(af, rslot[1]);
            ag = addf2(ag, rslot[2]);
            ao = addf2(ao, rslot[3]);

            float i0, i1, f0, f1, g0, g1, o0, o1;
            unpack2(ai, i0, i1); unpack2(af, f0, f1);
            unpack2(ag, g0, g1); unpack2(ao, o0, o1);

            float I0 = sigf(i0), F0 = sigf(f0), Gt0 = tanhfast(g0), O0 = sigf(o0);
            float I1 = sigf(i1), F1 = sigf(f1), Gt1 = tanhfast(g1), O1 = sigf(o1);
            c0 = F0 * c0 + I0 * Gt0;
            c1 = F1 * c1 + I1 * Gt1;
            float h0 = O0 * tanhfast(c0);
            float h1 = O1 * tanhfast(c1);

            *(float2*)&g_h[dir][(t + 1) & 1][u][b0g] = make_float2(h0, h1);

            // js=0 group barrier, then publish step completion
            asm volatile("bar.sync 1, 128;" ::: "memory");
            if (tid == 0) {
                __threadfence();
                stg_relaxed(&g_flag[dir][c6], (unsigned)(t + 1));
            }
        }
    }

    if (js == 0)
        *(float2*)&g_c[dir][u][b0g] = make_float2(c0, c1);
}

// ============================================================================
// Kernel 3: logits = [h_fwd, h_bwd] @ W_out + b_out, then softmax.
// 256 threads = 4 u-quarters x 64 batches; unroll-8 for MLP; smem reduce.
// ============================================================================
__global__ void __launch_bounds__(256) out_kernel(
    const float* __restrict__ W_out, const float* __restrict__ b_out,
    float* __restrict__ out)
{
    __shared__ float ws[2 * HN * NLAB];     // 20 KB
    __shared__ float red[4][BATCHN][NLAB];  // 10 KB
    const int tid = threadIdx.x;
    for (int i = tid; i < 2 * HN * NLAB; i += 256) ws[i] = W_out[i];
    __syncthreads();

    const int q   = tid >> 6;       // u-quarter 0..3
    const int b   = tid & 63;
    const int dir = q >> 1;
    const int ub  = (q & 1) * 128;

    float acc[NLAB];
#pragma unroll
    for (int l = 0; l < NLAB; ++l) acc[l] = 0.0f;

#pragma unroll 8
    for (int uu = 0; uu < 128; ++uu) {
        int u = ub + uu;
        float hv = g_h[dir][0][u][b];
        const float* w = ws + (dir * HN + u) * NLAB;
#pragma unroll
        for (int l = 0; l < NLAB; ++l) acc[l] += hv * w[l];
    }
#pragma unroll
    for (int l = 0; l < NLAB; ++l) red[q][b][l] = acc[l];
    __syncthreads();

    if (tid < BATCHN) {
        float a[NLAB];
#pragma unroll
        for (int l = 0; l < NLAB; ++l)
            a[l] = b_out[l] + red[0][tid][l] + red[1][tid][l]
                 + red[2][tid][l] + red[3][tid][l];
        float m = a[0];
#pragma unroll
        for (int l = 1; l < NLAB; ++l) m = fmaxf(m, a[l]);
        float s = 0.0f;
#pragma unroll
        for (int l = 0; l < NLAB; ++l) { a[l] = expf(a[l] - m); s += a[l]; }
        float inv = 1.0f / s;
#pragma unroll
        for (int l = 0; l < NLAB; ++l) out[tid * NLAB + l] = a[l] * inv;
    }
}

// ============================================================================
extern "C" void kernel_launch(void* const* d_in, const int* in_sizes, int n_in,
                              void* d_out, int out_size)
{
    const int*   tokens = (const int*)  d_in[0];
    const float* emb    = (const float*)d_in[1];
    const float* Wx_f   = (const float*)d_in[2];
    const float* Wh_f   = (const float*)d_in[3];
    const float* b_f    = (const float*)d_in[4];
    const float* Wx_b   = (const float*)d_in[5];
    const float* Wh_b   = (const float*)d_in[6];
    const float* b_b    = (const float*)d_in[7];
    const float* W_out  = (const float*)d_in[8];
    const float* b_out  = (const float*)d_in[9];
    float* out = (float*)d_out;

    const int lstm_smem = 65536 + 32768 + 4096;   // 100 KB
    cudaFuncSetAttribute(lstm_kernel,
                         cudaFuncAttributeMaxDynamicSharedMemorySize, lstm_smem);

    zx_gemm_kernel<<<4096, 256>>>(tokens, emb, Wx_f, b_f, Wx_b, b_b);
    for (int k = 0; k < NSUB; ++k)
        lstm_kernel<<<128, 256, lstm_smem>>>(Wh_f, Wh_b, k * STEPS);
    out_kernel<<<1, 256>>>(W_out, b_out, out);
}

// round 11
// speedup vs baseline: 1.3661x; 1.3661x over previous
#include <cuda_runtime.h>
#include <cstdint>

#define BATCHN 64
#define SEQN   512
#define EMBN   256
#define HN     256
#define G4N    1024   // 4*H
#define NCOL   2048   // both directions' gate columns
#define NLAB   10
#define STEPS  256    // steps per lstm sub-kernel
#define NSUB   (SEQN / STEPS)

// ---------------- scratch (device globals; no runtime allocation) ----------
__device__ float g_zx[(size_t)SEQN * BATCHN * NCOL];   // [t][b][col2]  (268 MB)
__device__ float g_h[2][2][HN][BATCHN];                // [dir][buf][unit][batch]
__device__ float g_c[2][HN][BATCHN];                   // cell state across sub-kernels
__device__ unsigned int          g_bar_count;          // zero-init, self-resetting
__device__ volatile unsigned int g_bar_gen;            // monotonic across replays

// one flag per 128B L2 line: kills the poll-contention hot line
struct __align__(128) PadFlag { unsigned v; unsigned pad[31]; };
__device__ PadFlag g_flag[2][64];

// ---------------- f32x2 helpers -------------------------------------------
__device__ __forceinline__ uint64_t pack2(float lo, float hi) {
    uint64_t r;
    asm("mov.b64 %0, {%1, %2};" : "=l"(r)
        : "r"(__float_as_uint(lo)), "r"(__float_as_uint(hi)));
    return r;
}
__device__ __forceinline__ void unpack2(uint64_t v, float& lo, float& hi) {
    unsigned a, b;
    asm("mov.b64 {%0, %1}, %2;" : "=r"(a), "=r"(b) : "l"(v));
    lo = __uint_as_float(a); hi = __uint_as_float(b);
}
__device__ __forceinline__ uint64_t ffma2(uint64_t a, uint64_t b, uint64_t c) {
    uint64_t d;
    asm("fma.rn.f32x2 %0, %1, %2, %3;" : "=l"(d) : "l"(a), "l"(b), "l"(c));
    return d;
}
__device__ __forceinline__ uint64_t addf2(uint64_t a, uint64_t b) {
    uint64_t d;
    asm("add.rn.f32x2 %0, %1, %2;" : "=l"(d) : "l"(a), "l"(b));
    return d;
}
__device__ __forceinline__ unsigned ldg_acquire(const unsigned* p) {
    unsigned v;
    asm volatile("ld.acquire.gpu.global.u32 %0, [%1];" : "=r"(v) : "l"(p));
    return v;
}
__device__ __forceinline__ void stg_release(unsigned* p, unsigned v) {
    asm volatile("st.release.gpu.global.u32 [%0], %1;" :: "l"(p), "r"(v));
}
__device__ __forceinline__ void stg_relaxed(unsigned* p, unsigned v) {
    asm volatile("st.relaxed.gpu.global.u32 [%0], %1;" :: "l"(p), "r"(v));
}

__device__ __forceinline__ float sigf(float x) {
    return __fdividef(1.0f, 1.0f + __expf(-x));
}
__device__ __forceinline__ float tanhfast(float x) {
    float e = __expf(2.0f * x);
    return 1.0f - 2.0f * __fdividef(1.0f, e + 1.0f);
}

// ---------------- grid barrier (lstm sub-kernel 0 only; gen monotonic) ----
__device__ __forceinline__ void grid_barrier() {
    __syncthreads();
    if (threadIdx.x == 0) {
        __threadfence();
        unsigned gen = g_bar_gen;
        if (atomicAdd(&g_bar_count, 1u) == gridDim.x - 1u) {
            g_bar_count = 0;
            __threadfence();
            g_bar_gen = gen + 1u;
        } else {
            while (g_bar_gen == gen) { __nanosleep(32); }
        }
        __threadfence();
    }
    __syncthreads();
}

// ============================================================================
// Kernel 1: zx = gather(emb, tokens) @ [Wx_f||Wx_b] + bias
// GEMM M=32768, N=2048, K=256; CTA tile 128x128, thread tile 8Mx8N (f32x2
// over M-pairs).  K-chunk 32 -> 33 KB smem -> 2 CTAs/SM.
// ============================================================================
__global__ void __launch_bounds__(256, 2) zx_gemm_kernel(
    const int*   __restrict__ tokens,
    const float* __restrict__ emb,
    const float* __restrict__ Wx_f, const float* __restrict__ b_f,
    const float* __restrict__ Wx_b, const float* __restrict__ b_b)
{
    __shared__ uint64_t a2_s[32 * 64];   // [k][m-pair] packed {m,m+1}  16 KB
    __shared__ float    b_s[32][128];    // [k][n]                     16 KB
    __shared__ int      tok_s[128];

    const int tid    = threadIdx.x;
    const int mtile  = blockIdx.x >> 4;      // 0..255
    const int ntile  = blockIdx.x & 15;      // 0..15
    const int n2base = ntile * 128;
    const float* wsrc = (n2base < G4N) ? (Wx_f + n2base) : (Wx_b + (n2base - G4N));

    if (tid < 128) {
        int gm = mtile * 128 + tid;          // m = t*64 + b
        tok_s[tid] = tokens[(gm & 63) * SEQN + (gm >> 6)];
    }
    __syncthreads();

    const int mp0 = (tid & 15) * 4;   // m-pair base (4 pairs = 8 rows)
    const int n0  = (tid >> 4) * 8;   // n base (8 cols)

    uint64_t acc[4][8];
#pragma unroll
    for (int p = 0; p < 4; ++p)
#pragma unroll
        for (int j = 0; j < 8; ++j) acc[p][j] = 0ull;

    for (int kc = 0; kc < 8; ++kc) {
        const int kbase = kc * 32;
        if (kc) __syncthreads();

        // stage A: gather 2 emb rows per m-pair, pack f32x2, transpose
#pragma unroll
        for (int i = 0; i < 2; ++i) {
            int task = tid + i * 256;        // 0..511
            int mp   = task & 63;
            int col4 = task >> 6;            // 0..7
            const float* r0 = emb + (size_t)tok_s[2*mp]   * EMBN + kbase + col4*4;
            const float* r1 = emb + (size_t)tok_s[2*mp+1] * EMBN + kbase + col4*4;
            float4 va = *(const float4*)r0;
            float4 vb = *(const float4*)r1;
            a2_s[(col4*4 + 0) * 64 + mp] = pack2(va.x, vb.x);
            a2_s[(col4*4 + 1) * 64 + mp] = pack2(va.y, vb.y);
            a2_s[(col4*4 + 2) * 64 + mp] = pack2(va.z, vb.z);
            a2_s[(col4*4 + 3) * 64 + mp] = pack2(va.w, vb.w);
        }
        // stage B
#pragma unroll
        for (int i = 0; i < 4; ++i) {
            int f4  = tid + i * 256;         // 0..1023
            int row = f4 >> 5;               // 0..31
            int c4  = f4 & 31;
            *(float4*)&b_s[row][c4 * 4] =
                *(const float4*)(wsrc + (size_t)(kbase + row) * G4N + c4 * 4);
        }
        __syncthreads();

#pragma unroll 4
        for (int k = 0; k < 32; ++k) {
            const uint64_t* ak = a2_s + k * 64 + mp0;
            ulonglong2 a01 = *(const ulonglong2*)ak;
            ulonglong2 a23 = *(const ulonglong2*)(ak + 2);
            float4 bv0 = *(const float4*)&b_s[k][n0];
            float4 bv1 = *(const float4*)&b_s[k][n0 + 4];
            uint64_t bb0 = pack2(bv0.x, bv0.x);
            uint64_t bb1 = pack2(bv0.y, bv0.y);
            uint64_t bb2 = pack2(bv0.z, bv0.z);
            uint64_t bb3 = pack2(bv0.w, bv0.w);
            uint64_t bb4 = pack2(bv1.x, bv1.x);
            uint64_t bb5 = pack2(bv1.y, bv1.y);
            uint64_t bb6 = pack2(bv1.z, bv1.z);
            uint64_t bb7 = pack2(bv1.w, bv1.w);
#pragma unroll
            for (int p = 0; p < 4; ++p) {
                uint64_t av = (p == 0) ? a01.x : (p == 1) ? a01.y
                             : (p == 2) ? a23.x : a23.y;
                acc[p][0] = ffma2(av, bb0, acc[p][0]);
                acc[p][1] = ffma2(av, bb1, acc[p][1]);
                acc[p][2] = ffma2(av, bb2, acc[p][2]);
                acc[p][3] = ffma2(av, bb3, acc[p][3]);
                acc[p][4] = ffma2(av, bb4, acc[p][4]);
                acc[p][5] = ffma2(av, bb5, acc[p][5]);
                acc[p][6] = ffma2(av, bb6, acc[p][6]);
                acc[p][7] = ffma2(av, bb7, acc[p][7]);
            }
        }
    }

    // epilogue: + bias, store
    float bias[8];
#pragma unroll
    for (int j = 0; j < 8; ++j) {
        int col2 = n2base + n0 + j;
        bias[j] = (col2 < G4N) ? b_f[col2] : b_b[col2 - G4N];
    }
#pragma unroll
    for (int p = 0; p < 4; ++p) {
        float lo[8], hi[8];
#pragma unroll
        for (int j = 0; j < 8; ++j) {
            unpack2(acc[p][j], lo[j], hi[j]);
            lo[j] += bias[j]; hi[j] += bias[j];
        }
        size_t m = (size_t)(mtile * 128 + 2 * (mp0 + p));
        float* dst = g_zx + m * NCOL + n2base + n0;
        *(float4*)(dst)            = make_float4(lo[0], lo[1], lo[2], lo[3]);
        *(float4*)(dst + 4)        = make_float4(lo[4], lo[5], lo[6], lo[7]);
        *(float4*)(dst + NCOL)     = make_float4(hi[0], hi[1], hi[2], hi[3]);
        *(float4*)(dst + NCOL + 4) = make_float4(hi[4], hi[5], hi[6], hi[7]);
    }
}

// ============================================================================
// Kernel 2 (x2): bidirectional LSTM recurrence, STEPS steps per launch.
// 128 CTAs x 256 threads.  CTA = (dir, unit-group of 8, batch-half of 32).
// Sync: wait ALL 32 same-batch-half flags (wait set covers all h readers ->
// WAR-safe with 2-deep g_h).  Flags padded to 128B lines; release/acquire.
// js(2 j-halves) x ul(8) x bp(16); partials reduced js=1 -> js=0 in smem.
// smem: wh2 64K | h_s 32K | red 4K = 100 KB dynamic.
// ============================================================================
__global__ void __launch_bounds__(256) lstm_kernel(
    const float* __restrict__ Wh_f, const float* __restrict__ Wh_b, int t0)
{
    extern __shared__ unsigned char smraw[];
    uint64_t* wh2 = (uint64_t*)smraw;                        // 64 KB [j][ul][g] {w,w}
    float (*h_s)[32] = (float(*)[32])(smraw + 65536);        // 32 KB [j][lb]
    uint64_t* red = (uint64_t*)(smraw + 98304);              // 4 KB  [ul][bp][4]

    const int tid = threadIdx.x;
    const int cid = blockIdx.x;
    const int dir = cid >> 6;
    const int c6  = cid & 63;
    const int ug  = c6 >> 1;            // 0..31
    const int bh  = c6 & 1;
    const int u0  = ug * 8;
    const int B0  = bh * 32;
    const float* Wh = dir ? Wh_b : Wh_f;

    // stage duplicated Wh pairs: wh2[j*32 + ul*4 + g] = {w,w}
    for (int idx = tid; idx < HN * 32; idx += 256) {
        int j  = idx >> 5;
        int ul = (idx >> 2) & 7;
        int g  = idx & 3;
        float w = Wh[j * G4N + g * HN + u0 + ul];
        wh2[idx] = pack2(w, w);
    }
    if (t0 == 0) {
        if (tid == 0) stg_relaxed(&g_flag[dir][c6].v, 0u);
        grid_barrier();                 // all flags reset before any poll
    } else {
        __syncthreads();
    }

    const int lane = tid & 31;
    const int wrp  = tid >> 5;
    const int js   = wrp >> 2;                           // j-half
    const int ul   = (wrp & 1) * 4 + (lane & 3);         // 0..7
    const int bp   = ((wrp >> 1) & 1) * 8 + (lane >> 2); // 0..15
    const int lb0  = bp * 2;
    const int b0g  = B0 + lb0;
    const int u    = u0 + ul;
    const uint64_t* wp = wh2 + ul * 4;
    const int jbase = js * 128;
    uint64_t* rslot = red + ((ul << 4) + bp) * 4;
    // flag this lane polls (lane<32 path): producer CTA c6 = lane*2 + bh
    const unsigned* fpoll = &g_flag[dir][lane * 2 + bh].v;

    float c0 = 0.0f, c1 = 0.0f;
    if (t0 > 0 && js == 0) {
        float2 cc = *(float2*)&g_c[dir][u][b0g];
        c0 = cc.x; c1 = cc.y;
    }

    for (int t = t0; t < t0 + STEPS; ++t) {
        const int zt = dir ? (SEQN - 1 - t) : t;
        // z preloads (js=0 only); independent of h -> overlap wait+stage
        float zi0, zf0, zg0, zo0, zi1, zf1, zg1, zo1;
        if (js == 0) {
            const float* zrow = g_zx + ((size_t)zt * BATCHN + b0g) * NCOL
                                    + dir * G4N + u;
            zi0 = __ldg(zrow + 0 * HN);        zf0 = __ldg(zrow + 1 * HN);
            zg0 = __ldg(zrow + 2 * HN);        zo0 = __ldg(zrow + 3 * HN);
            zi1 = __ldg(zrow + NCOL + 0 * HN); zf1 = __ldg(zrow + NCOL + 1 * HN);
            zg1 = __ldg(zrow + NCOL + 2 * HN); zo1 = __ldg(zrow + NCOL + 3 * HN);
        }

        if (t > 0) {
            // wait on ALL 32 same-batch-half CTAs (producers AND readers);
            // acquire-load establishes ordering for the staged h reads below
            if (tid < 32) {
                unsigned ok;
                do {
                    unsigned v = ldg_acquire(fpoll);
                    ok = __all_sync(0xffffffffu, v >= (unsigned)t);
                } while (!ok);
            }
            __syncthreads();
            // stage h_prev for this batch half (32 KB) from L2
#pragma unroll
            for (int i = 0; i < 8; ++i) {
                int f4  = tid + i * 256;
                int j   = f4 >> 3;
                int lb4 = f4 & 7;
                *(float4*)&h_s[j][lb4 * 4] =
                    __ldcg((const float4*)&g_h[dir][t & 1][j][B0 + lb4 * 4]);
            }
            __syncthreads();
        }

        uint64_t ai, af, ag, ao;
        if (js == 0) {
            ai = pack2(zi0, zi1); af = pack2(zf0, zf1);
            ag = pack2(zg0, zg1); ao = pack2(zo0, zo1);
        } else {
            ai = af = ag = ao = 0ull;
        }

        if (t > 0) {
#pragma unroll 8
            for (int j = 0; j < 128; ++j) {
                const int jj = jbase + j;
                uint64_t h2 = *(const uint64_t*)&h_s[jj][lb0];
                ulonglong2 w01 = *(const ulonglong2*)(wp + jj * 32);
                ulonglong2 w23 = *(const ulonglong2*)(wp + jj * 32 + 2);
                ai = ffma2(h2, w01.x, ai);
                af = ffma2(h2, w01.y, af);
                ag = ffma2(h2, w23.x, ag);
                ao = ffma2(h2, w23.y, ao);
            }
        }

        // reduce js=1 partials into js=0
        if (js == 1) {
            rslot[0] = ai; rslot[1] = af; rslot[2] = ag; rslot[3] = ao;
        }
        __syncthreads();
        if (js == 0) {
            ai = addf2(ai, rslot[0]);
            af = addf2(af, rslot[1]);
            ag = addf2(ag, rslot[2]);
            ao = addf2(ao, rslot[3]);

            float i0, i1, f0, f1, g0, g1, o0, o1;
            unpack2(ai, i0, i1); unpack2(af, f0, f1);
            unpack2(ag, g0, g1); unpack2(ao, o0, o1);

            float I0 = sigf(i0), F0 = sigf(f0), Gt0 = tanhfast(g0), O0 = sigf(o0);
            float I1 = sigf(i1), F1 = sigf(f1), Gt1 = tanhfast(g1), O1 = sigf(o1);
            c0 = F0 * c0 + I0 * Gt0;
            c1 = F1 * c1 + I1 * Gt1;
            float h0 = O0 * tanhfast(c0);
            float h1 = O1 * tanhfast(c1);

            *(float2*)&g_h[dir][(t + 1) & 1][u][b0g] = make_float2(h0, h1);

            // js=0 group barrier (h stores done), then release-publish
            asm volatile("bar.sync 1, 128;" ::: "memory");
            if (tid == 0)
                stg_release(&g_flag[dir][c6].v, (unsigned)(t + 1));
        }
    }

    if (js == 0)
        *(float2*)&g_c[dir][u][b0g] = make_float2(c0, c1);
}

// ============================================================================
// Kernel 3: logits = [h_fwd, h_bwd] @ W_out + b_out, then softmax.
// 256 threads = 4 u-quarters x 64 batches; unroll-8 for MLP; smem reduce.
// ============================================================================
__global__ void __launch_bounds__(256) out_kernel(
    const float* __restrict__ W_out, const float* __restrict__ b_out,
    float* __restrict__ out)
{
    __shared__ float ws[2 * HN * NLAB];     // 20 KB
    __shared__ float red[4][BATCHN][NLAB];  // 10 KB
    const int tid = threadIdx.x;
    for (int i = tid; i < 2 * HN * NLAB; i += 256) ws[i] = W_out[i];
    __syncthreads();

    const int q   = tid >> 6;       // u-quarter 0..3
    const int b   = tid & 63;
    const int dir = q >> 1;
    const int ub  = (q & 1) * 128;

    float acc[NLAB];
#pragma unroll
    for (int l = 0; l < NLAB; ++l) acc[l] = 0.0f;

#pragma unroll 8
    for (int uu = 0; uu < 128; ++uu) {
        int u = ub + uu;
        float hv = g_h[dir][0][u][b];
        const float* w = ws + (dir * HN + u) * NLAB;
#pragma unroll
        for (int l = 0; l < NLAB; ++l) acc[l] += hv * w[l];
    }
#pragma unroll
    for (int l = 0; l < NLAB; ++l) red[q][b][l] = acc[l];
    __syncthreads();

    if (tid < BATCHN) {
        float a[NLAB];
#pragma unroll
        for (int l = 0; l < NLAB; ++l)
            a[l] = b_out[l] + red[0][tid][l] + red[1][tid][l]
                 + red[2][tid][l] + red[3][tid][l];
        float m = a[0];
#pragma unroll
        for (int l = 1; l < NLAB; ++l) m = fmaxf(m, a[l]);
        float s = 0.0f;
#pragma unroll
        for (int l = 0; l < NLAB; ++l) { a[l] = expf(a[l] - m); s += a[l]; }
        float inv = 1.0f / s;
#pragma unroll
        for (int l = 0; l < NLAB; ++l) out[tid * NLAB + l] = a[l] * inv;
    }
}

// ============================================================================
extern "C" void kernel_launch(void* const* d_in, const int* in_sizes, int n_in,
                              void* d_out, int out_size)
{
    const int*   tokens = (const int*)  d_in[0];
    const float* emb    = (const float*)d_in[1];
    const float* Wx_f   = (const float*)d_in[2];
    const float* Wh_f   = (const float*)d_in[3];
    const float* b_f    = (const float*)d_in[4];
    const float* Wx_b   = (const float*)d_in[5];
    const float* Wh_b   = (const float*)d_in[6];
    const float* b_b    = (const float*)d_in[7];
    const float* W_out  = (const float*)d_in[8];
    const float* b_out  = (const float*)d_in[9];
    float* out = (float*)d_out;

    const int lstm_smem = 65536 + 32768 + 4096;   // 100 KB
    cudaFuncSetAttribute(lstm_kernel,
                         cudaFuncAttributeMaxDynamicSharedMemorySize, lstm_smem);

    zx_gemm_kernel<<<4096, 256>>>(tokens, emb, Wx_f, b_f, Wx_b, b_b);
    for (int k = 0; k < NSUB; ++k)
        lstm_kernel<<<128, 256, lstm_smem>>>(Wh_f, Wh_b, k * STEPS);
    out_kernel<<<1, 256>>>(W_out, b_out, out);
}